// round 2
// baseline (speedup 1.0000x reference)
#include <cuda_runtime.h>
#include <cuda_bf16.h>

#define NSAMPLE 32
#define MAXN 8192
#define RADIUS2 1.0f

// Scratch (no allocations allowed)
__device__ int g_ball[MAXN * NSAMPLE];
__device__ int g_cnt[MAXN];
__device__ int g_off[MAXN + 1];
__device__ unsigned long long g_bm[MAXN];

// sum of squares with explicit mul-then-left-assoc-add (no fma contraction),
// matching XLA's elementwise square + axis reduce.
__device__ __forceinline__ float sq3(float ax, float ay, float az) {
    return __fadd_rn(__fadd_rn(__fmul_rn(ax, ax), __fmul_rn(ay, ay)), __fmul_rn(az, az));
}

// ---------------------------------------------------------------------------
// Kernel 1: per-point 64-bit roi membership mask
// ---------------------------------------------------------------------------
__global__ void mask_kernel(const float* __restrict__ xyz,
                            const float* __restrict__ rois,
                            int N, int Nb, int M) {
    int n = blockIdx.x * blockDim.x + threadIdx.x;
    if (n >= N) return;
    int b = n / Nb;
    float px = xyz[3 * n + 0], py = xyz[3 * n + 1], pz = xyz[3 * n + 2];
    const float* r = rois + (size_t)b * M * 7;
    unsigned long long bm = 0ull;
    for (int m = 0; m < M; m++) {
        float cx = r[m * 7 + 0], cy = r[m * 7 + 1], cz = r[m * 7 + 2];
        float dx = r[m * 7 + 3], dy = r[m * 7 + 4], dz = r[m * 7 + 5];
        float r2 = sq3(dx, dy, dz);
        float d2 = sq3(__fsub_rn(px, cx), __fsub_rn(py, cy), __fsub_rn(pz, cz));
        if (d2 <= r2) bm |= (1ull << m);
    }
    g_bm[n] = bm;
}

// ---------------------------------------------------------------------------
// Kernel 2: warp-per-point ordered ball query (first NSAMPLE hits in j order)
// ---------------------------------------------------------------------------
__global__ void query_kernel(const float* __restrict__ xyz,
                             const float* __restrict__ new_xyz,
                             int N, int Nb, int M, int K) {
    int gw = (blockIdx.x * blockDim.x + threadIdx.x) >> 5;
    int lane = threadIdx.x & 31;
    if (gw >= N) return;
    int n = gw;
    int b = n / Nb;
    float px = xyz[3 * n + 0], py = xyz[3 * n + 1], pz = xyz[3 * n + 2];
    unsigned long long bm = g_bm[n];
    int count = 0;
    int* outp = g_ball + n * NSAMPLE;
    int baseMK = b * M * K;
    while (bm && count < NSAMPLE) {
        int m = __ffsll((long long)bm) - 1;
        bm &= bm - 1ull;
        const float* g = new_xyz + ((size_t)(b * M + m)) * K * 3;
        for (int k0 = 0; k0 < K && count < NSAMPLE; k0 += 32) {
            int k = k0 + lane;
            bool ok = false;
            if (k < K) {
                float gx = g[3 * k + 0], gy = g[3 * k + 1], gz = g[3 * k + 2];
                float d2 = sq3(__fsub_rn(px, gx), __fsub_rn(py, gy), __fsub_rn(pz, gz));
                ok = (d2 <= RADIUS2);
            }
            unsigned bits = __ballot_sync(0xffffffffu, ok);
            int rank = count + __popc(bits & ((1u << lane) - 1u));
            if (ok && rank < NSAMPLE) outp[rank] = baseMK + m * K + k;
            count += __popc(bits);
        }
    }
    if (lane == 0) g_cnt[n] = count < NSAMPLE ? count : NSAMPLE;
}

// ---------------------------------------------------------------------------
// Kernel 3: single-block exclusive scan of g_cnt (N <= 8192)
// ---------------------------------------------------------------------------
__global__ void scan_kernel(int N) {
    __shared__ int sh[1024];
    int tid = threadIdx.x;
    int per = (N + 1023) / 1024;   // <= 8
    int base = tid * per;
    int loc[8];
    int s = 0;
    for (int i = 0; i < per; i++) {
        int v = (base + i < N) ? g_cnt[base + i] : 0;
        loc[i] = v;
        s += v;
    }
    sh[tid] = s;
    __syncthreads();
    for (int d = 1; d < 1024; d <<= 1) {
        int t = (tid >= d) ? sh[tid - d] : 0;
        __syncthreads();
        sh[tid] += t;
        __syncthreads();
    }
    int run = sh[tid] - s;   // exclusive prefix for this chunk
    for (int i = 0; i < per; i++) {
        if (base + i < N) g_off[base + i] = run;
        run += loc[i];
    }
    if (tid == 1023) g_off[N] = sh[1023];
}

// ---------------------------------------------------------------------------
// Kernel 4: zero-fill entire output (output is poisoned to 0xAA)
// ---------------------------------------------------------------------------
__global__ void zero_kernel(float* __restrict__ out, int total) {
    int i = blockIdx.x * blockDim.x + threadIdx.x;
    int n4 = total >> 2;
    if (i < n4) ((float4*)out)[i] = make_float4(0.f, 0.f, 0.f, 0.f);
    int rem = total & 3;
    if (i < rem) out[n4 * 4 + i] = 0.f;
}

// ---------------------------------------------------------------------------
// Kernel 5: gather valid rows. one warp per (n, s) candidate slot.
// ---------------------------------------------------------------------------
__global__ void gather_kernel(const float* __restrict__ xyz,
                              const float* __restrict__ new_xyz,
                              const float* __restrict__ feat,
                              float* __restrict__ out_group,
                              float* __restrict__ out_idx,
                              int N, int C, int has_idx) {
    int gw = (blockIdx.x * blockDim.x + threadIdx.x) >> 5;
    int lane = threadIdx.x & 31;
    int n = gw >> 5;           // / NSAMPLE
    int s = gw & (NSAMPLE - 1);
    if (n >= N) return;
    if (s >= g_cnt[n]) return;
    int pos = g_off[n] + s;
    int gi = g_ball[n * NSAMPLE + s];
    int W = 3 + C;
    float* row = out_group + (size_t)pos * W;
    for (int c = lane; c < W; c += 32) {
        float v;
        if (c < 3) v = __fsub_rn(xyz[3 * n + c], new_xyz[3 * (size_t)gi + c]);
        else       v = feat[(size_t)n * C + (c - 3)];
        row[c] = v;
    }
    if (lane == 0 && has_idx) out_idx[pos] = (float)gi;
}

// ---------------------------------------------------------------------------
extern "C" void kernel_launch(void* const* d_in, const int* in_sizes, int n_in,
                              void* d_out, int out_size) {
    const float* xyz      = (const float*)d_in[0];
    const float* new_xyz  = (const float*)d_in[2];
    const float* rois     = (const float*)d_in[3];
    const float* features = (const float*)d_in[4];

    int N  = in_sizes[0] / 3;
    int B  = in_sizes[1];
    int M  = in_sizes[3] / (7 * B);
    int K  = in_sizes[2] / (3 * B * M);
    int C  = in_sizes[4] / N;
    int Nb = N / B;
    int L  = N * NSAMPLE;
    int W  = 3 + C;

    float* out = (float*)d_out;
    int has_idx = (out_size >= L * W + L) ? 1 : 0;
    float* out_idx = out + (size_t)L * W;

    // 1. roi membership masks
    mask_kernel<<<(N + 255) / 256, 256>>>(xyz, rois, N, Nb, M);
    // 2. ordered ball query, warp per point
    {
        int warps = N;
        int blocks = (warps * 32 + 255) / 256;
        query_kernel<<<blocks, 256>>>(xyz, new_xyz, N, Nb, M, K);
    }
    // 3. exclusive scan of counts
    scan_kernel<<<1, 1024>>>(N);
    // 4. zero entire output
    {
        int n4 = (out_size >> 2) + 4;
        zero_kernel<<<(n4 + 255) / 256, 256>>>(out, out_size);
    }
    // 5. gather valid rows
    {
        int warps = N * NSAMPLE;
        int blocks = (warps * 32 + 255) / 256;
        gather_kernel<<<blocks, 256>>>(xyz, new_xyz, features, out, out_idx,
                                       N, C, has_idx);
    }
}

// round 3
// speedup vs baseline: 1.1645x; 1.1645x over previous
#include <cuda_runtime.h>
#include <cuda_bf16.h>

#define NSAMPLE 32
#define MAXN 8192
#define RADIUS2 1.0f

// Scratch (no allocations allowed)
__device__ int g_ball[MAXN * NSAMPLE];
__device__ int g_cnt[MAXN];
__device__ int g_off[MAXN + 1];
__device__ int g_done = 0;

// sum of squares with explicit mul-then-left-assoc-add (no fma contraction),
// matching XLA's elementwise square + axis reduce.
__device__ __forceinline__ float sq3(float ax, float ay, float az) {
    return __fadd_rn(__fadd_rn(__fmul_rn(ax, ax), __fmul_rn(ay, ay)), __fmul_rn(az, az));
}

// ---------------------------------------------------------------------------
// Kernel 1: fused roi-mask + ordered ball query + count, with last-block scan.
// One warp per point. 8 warps / block.
// ---------------------------------------------------------------------------
__global__ void __launch_bounds__(256) query_scan_kernel(
        const float* __restrict__ xyz,
        const float* __restrict__ new_xyz,
        const float* __restrict__ rois,
        int N, int Nb, int M, int K) {
    int lane = threadIdx.x & 31;
    int wid  = threadIdx.x >> 5;
    int n    = blockIdx.x * 8 + wid;

    if (n < N) {
        int b = n / Nb;
        float px = xyz[3 * n + 0], py = xyz[3 * n + 1], pz = xyz[3 * n + 2];

        // --- roi membership bitmask via per-lane checks + ballot ---
        const float* r = rois + (size_t)b * M * 7;
        unsigned long long bm = 0ull;
        for (int mb = 0; mb < M; mb += 32) {
            int m = mb + lane;
            bool in = false;
            if (m < M) {
                float cx = r[m * 7 + 0], cy = r[m * 7 + 1], cz = r[m * 7 + 2];
                float dx = r[m * 7 + 3], dy = r[m * 7 + 4], dz = r[m * 7 + 5];
                float r2 = sq3(dx, dy, dz);
                float d2 = sq3(__fsub_rn(px, cx), __fsub_rn(py, cy), __fsub_rn(pz, cz));
                in = (d2 <= r2);
            }
            unsigned bits = __ballot_sync(0xffffffffu, in);
            bm |= ((unsigned long long)bits) << mb;
        }

        // --- ordered ball query: first NSAMPLE hits in j = m*K + k order ---
        int count = 0;
        int* outp = g_ball + n * NSAMPLE;
        int baseMK = b * M * K;
        while (bm && count < NSAMPLE) {
            int m = __ffsll((long long)bm) - 1;
            bm &= bm - 1ull;
            const float* g = new_xyz + ((size_t)(b * M + m)) * K * 3;
            for (int k0 = 0; k0 < K && count < NSAMPLE; k0 += 32) {
                int k = k0 + lane;
                bool ok = false;
                if (k < K) {
                    float gx = g[3 * k + 0], gy = g[3 * k + 1], gz = g[3 * k + 2];
                    float d2 = sq3(__fsub_rn(px, gx), __fsub_rn(py, gy), __fsub_rn(pz, gz));
                    ok = (d2 <= RADIUS2);
                }
                unsigned bits = __ballot_sync(0xffffffffu, ok);
                int rank = count + __popc(bits & ((1u << lane) - 1u));
                if (ok && rank < NSAMPLE) outp[rank] = baseMK + m * K + k;
                count += __popc(bits);
            }
        }
        if (lane == 0) {
            g_cnt[n] = count < NSAMPLE ? count : NSAMPLE;
            __threadfence();   // make this warp's cnt/ball globally visible
        }
    }

    // --- last-block-done: the final block performs the exclusive scan ---
    __shared__ int sh_isLast;
    __syncthreads();
    if (threadIdx.x == 0) {
        int t = atomicAdd(&g_done, 1);
        sh_isLast = (t == (int)gridDim.x - 1) ? 1 : 0;
    }
    __syncthreads();
    if (!sh_isLast) return;

    // scan of g_cnt[0..N) -> g_off (exclusive), g_off[N] = total. 256 threads.
    int tid = threadIdx.x;
    int per = (N + 255) / 256;           // <= 32 for MAXN=8192
    int base = tid * per;
    int loc[32];
    int s = 0;
    #pragma unroll 4
    for (int i = 0; i < per; i++) {
        int v = (base + i < N) ? __ldcg(&g_cnt[base + i]) : 0;
        loc[i] = v;
        s += v;
    }
    // warp inclusive scan of per-thread sums
    int pre = s;
    #pragma unroll
    for (int d = 1; d < 32; d <<= 1) {
        int t = __shfl_up_sync(0xffffffffu, pre, d);
        if (lane >= d) pre += t;
    }
    __shared__ int wsum[8];
    if (lane == 31) wsum[wid] = pre;
    __syncthreads();
    if (tid == 0) {
        int acc = 0;
        #pragma unroll
        for (int w = 0; w < 8; w++) { int t = wsum[w]; wsum[w] = acc; acc += t; }
    }
    __syncthreads();
    int run = wsum[wid] + (pre - s);     // exclusive prefix for this chunk
    #pragma unroll 4
    for (int i = 0; i < per; i++) {
        if (base + i < N) g_off[base + i] = run;
        run += loc[i];
    }
    if (tid == 255) g_off[N] = run;      // grand total (pads are zero)
    if (tid == 0) g_done = 0;            // reset for next graph replay
}

// ---------------------------------------------------------------------------
// Kernel 2: fused gather + tail-zero. One warp per slot gw in [0, L):
//   slot job: (n = gw/32, s = gw%32); if s < cnt[n] write row off[n]+s.
//   zero job: if gw >= total, zero row gw.
// Every output row is written exactly once.
// ---------------------------------------------------------------------------
__global__ void __launch_bounds__(256) gather_zero_kernel(
        const float* __restrict__ xyz,
        const float* __restrict__ new_xyz,
        const float* __restrict__ feat,
        float* __restrict__ out_group,
        float* __restrict__ out_idx,
        int N, int C, int has_idx) {
    int gw   = (blockIdx.x * blockDim.x + threadIdx.x) >> 5;
    int lane = threadIdx.x & 31;
    int L = N * NSAMPLE;
    if (gw >= L) return;
    int total = g_off[N];
    int W = 3 + C;

    // --- slot job ---
    int n = gw >> 5;
    int s = gw & (NSAMPLE - 1);
    if (s < g_cnt[n]) {
        int pos = g_off[n] + s;
        int gi  = g_ball[n * NSAMPLE + s];
        float* row = out_group + (size_t)pos * W;
        for (int c = lane; c < W; c += 32) {
            float v;
            if (c < 3) v = __fsub_rn(xyz[3 * n + c], new_xyz[3 * (size_t)gi + c]);
            else       v = feat[(size_t)n * C + (c - 3)];
            row[c] = v;
        }
        if (lane == 0 && has_idx) out_idx[pos] = (float)gi;
    }

    // --- zero job: row gw is past the valid prefix ---
    if (gw >= total) {
        float* row = out_group + (size_t)gw * W;
        for (int c = lane; c < W; c += 32) row[c] = 0.f;
        if (lane == 0 && has_idx) out_idx[gw] = 0.f;
    }
}

// ---------------------------------------------------------------------------
extern "C" void kernel_launch(void* const* d_in, const int* in_sizes, int n_in,
                              void* d_out, int out_size) {
    const float* xyz      = (const float*)d_in[0];
    const float* new_xyz  = (const float*)d_in[2];
    const float* rois     = (const float*)d_in[3];
    const float* features = (const float*)d_in[4];

    int N  = in_sizes[0] / 3;
    int B  = in_sizes[1];
    int M  = in_sizes[3] / (7 * B);
    int K  = in_sizes[2] / (3 * B * M);
    int C  = in_sizes[4] / N;
    int Nb = N / B;
    int L  = N * NSAMPLE;
    int W  = 3 + C;

    float* out = (float*)d_out;
    int has_idx = (out_size >= L * W + L) ? 1 : 0;
    float* out_idx = out + (size_t)L * W;

    // 1. fused mask + ordered ball query + count + (last block) scan
    {
        int blocks = (N + 7) / 8;          // 8 warps per 256-thread block
        query_scan_kernel<<<blocks, 256>>>(xyz, new_xyz, rois, N, Nb, M, K);
    }
    // 2. fused gather + tail-zero (single write of every output byte)
    {
        int warps = L;
        int blocks = (warps * 32 + 255) / 256;
        gather_zero_kernel<<<blocks, 256>>>(xyz, new_xyz, features, out, out_idx,
                                            N, C, has_idx);
    }
}

// round 6
// speedup vs baseline: 1.2321x; 1.0580x over previous
#include <cuda_runtime.h>
#include <cuda_bf16.h>

#define NSAMPLE 32
#define MAXN 8192
#define RADIUS2 1.0f

// Scratch (no allocations allowed)
__device__ int g_ball[MAXN * NSAMPLE];
__device__ int g_cnt[MAXN];
__device__ int g_off[MAXN + 1];
__device__ int g_done = 0;

// sum of squares with explicit mul-then-left-assoc-add (no fma contraction),
// matching XLA's elementwise square + axis reduce.
__device__ __forceinline__ float sq3(float ax, float ay, float az) {
    return __fadd_rn(__fadd_rn(__fmul_rn(ax, ax), __fmul_rn(ay, ay)), __fmul_rn(az, az));
}

// ---------------------------------------------------------------------------
// Kernel 1: fused roi-mask + ordered ball query + count, with last-block scan.
// One warp per point. 8 warps / block.
// ---------------------------------------------------------------------------
__global__ void __launch_bounds__(256) query_scan_kernel(
        const float* __restrict__ xyz,
        const float* __restrict__ new_xyz,
        const float* __restrict__ rois,
        int N, int Nb, int M, int K) {
    int lane = threadIdx.x & 31;
    int wid  = threadIdx.x >> 5;
    int n    = blockIdx.x * 8 + wid;

    if (n < N) {
        int b = n / Nb;
        float px = xyz[3 * n + 0], py = xyz[3 * n + 1], pz = xyz[3 * n + 2];

        // --- roi membership bitmask via per-lane checks + ballot ---
        const float* r = rois + (size_t)b * M * 7;
        unsigned long long bm = 0ull;
        for (int mb = 0; mb < M; mb += 32) {
            int m = mb + lane;
            bool in = false;
            if (m < M) {
                float cx = r[m * 7 + 0], cy = r[m * 7 + 1], cz = r[m * 7 + 2];
                float dx = r[m * 7 + 3], dy = r[m * 7 + 4], dz = r[m * 7 + 5];
                float r2 = sq3(dx, dy, dz);
                float d2 = sq3(__fsub_rn(px, cx), __fsub_rn(py, cy), __fsub_rn(pz, cz));
                in = (d2 <= r2);
            }
            unsigned bits = __ballot_sync(0xffffffffu, in);
            bm |= ((unsigned long long)bits) << mb;
        }

        // --- ordered ball query: first NSAMPLE hits in j = m*K + k order ---
        int count = 0;
        int* outp = g_ball + n * NSAMPLE;
        int baseMK = b * M * K;
        while (bm && count < NSAMPLE) {
            int m = __ffsll((long long)bm) - 1;
            bm &= bm - 1ull;
            const float* g = new_xyz + ((size_t)(b * M + m)) * K * 3;
            for (int k0 = 0; k0 < K && count < NSAMPLE; k0 += 32) {
                int k = k0 + lane;
                bool ok = false;
                if (k < K) {
                    float gx = g[3 * k + 0], gy = g[3 * k + 1], gz = g[3 * k + 2];
                    float d2 = sq3(__fsub_rn(px, gx), __fsub_rn(py, gy), __fsub_rn(pz, gz));
                    ok = (d2 <= RADIUS2);
                }
                unsigned bits = __ballot_sync(0xffffffffu, ok);
                int rank = count + __popc(bits & ((1u << lane) - 1u));
                if (ok && rank < NSAMPLE) outp[rank] = baseMK + m * K + k;
                count += __popc(bits);
            }
        }
        if (lane == 0) {
            g_cnt[n] = count < NSAMPLE ? count : NSAMPLE;
            __threadfence();   // make this warp's cnt/ball globally visible
        }
    }

    // --- last-block-done: the final block performs the exclusive scan ---
    __shared__ int sh_isLast;
    __syncthreads();
    if (threadIdx.x == 0) {
        int t = atomicAdd(&g_done, 1);
        sh_isLast = (t == (int)gridDim.x - 1) ? 1 : 0;
    }
    __syncthreads();
    if (!sh_isLast) return;

    // scan of g_cnt[0..N) -> g_off (exclusive), g_off[N] = total. 256 threads.
    int tid = threadIdx.x;
    int per = (N + 255) / 256;           // <= 32 for MAXN=8192
    int base = tid * per;
    int loc[32];
    int s = 0;
    #pragma unroll 4
    for (int i = 0; i < per; i++) {
        int v = (base + i < N) ? __ldcg(&g_cnt[base + i]) : 0;
        loc[i] = v;
        s += v;
    }
    // warp inclusive scan of per-thread sums
    int pre = s;
    #pragma unroll
    for (int d = 1; d < 32; d <<= 1) {
        int t = __shfl_up_sync(0xffffffffu, pre, d);
        if (lane >= d) pre += t;
    }
    __shared__ int wsum[8];
    if (lane == 31) wsum[wid] = pre;
    __syncthreads();
    if (tid == 0) {
        int acc = 0;
        #pragma unroll
        for (int w = 0; w < 8; w++) { int t = wsum[w]; wsum[w] = acc; acc += t; }
    }
    __syncthreads();
    int run = wsum[wid] + (pre - s);     // exclusive prefix for this chunk
    #pragma unroll 4
    for (int i = 0; i < per; i++) {
        if (base + i < N) g_off[base + i] = run;
        run += loc[i];
    }
    if (tid == 255) g_off[N] = run;      // grand total (pads are zero)
    if (tid == 0) g_done = 0;            // reset for next graph replay
}

// ---------------------------------------------------------------------------
// Kernel 2 (specialized W=35, C=32): warp-per-point flat coalesced gather,
// plus extra blocks that float4-zero the tail region concurrently.
// ---------------------------------------------------------------------------
__global__ void __launch_bounds__(256) gather35_kernel(
        const float* __restrict__ xyz,
        const float* __restrict__ new_xyz,
        const float* __restrict__ feat,
        float* __restrict__ out_group,
        float* __restrict__ out_idx,
        int N, int has_idx, int point_blocks, int zero_blocks, int L) {
    const int W = 35, C = 32;
    int lane = threadIdx.x & 31;

    if ((int)blockIdx.x < point_blocks) {
        // ---------------- gather: one warp per point ----------------
        int n = blockIdx.x * 8 + (threadIdx.x >> 5);
        if (n >= N) return;
        int cnt = g_cnt[n];
        if (cnt == 0) return;
        int off = g_off[n];

        int gi_l = g_ball[n * NSAMPLE + (lane < cnt ? lane : 0)];
        if (has_idx && lane < cnt) out_idx[off + lane] = (float)gi_l;

        float px = xyz[3 * n + 0], py = xyz[3 * n + 1], pz = xyz[3 * n + 2];
        float fv = feat[(size_t)n * C + lane];          // C == 32: one per lane

        int tot = cnt * W;                              // <= 1120
        float* base = out_group + (size_t)off * W;      // contiguous span
        int iters = (tot + 31) >> 5;
        for (int it = 0; it < iters; it++) {
            int e = (it << 5) + lane;
            int s = (int)(((unsigned)e * 59919u) >> 21);   // e / 35 (exact for e<=1154)
            int c = e - s * W;
            int gi = __shfl_sync(0xffffffffu, gi_l, s & 31);
            float fc = __shfl_sync(0xffffffffu, fv, (c - 3) & 31);
            if (e < tot) {
                float v;
                if (c < 3) {
                    float p = (c == 0) ? px : (c == 1) ? py : pz;
                    v = __fsub_rn(p, __ldg(&new_xyz[3 * (size_t)gi + c]));
                } else {
                    v = fc;
                }
                base[e] = v;
            }
        }
    } else {
        // ---------------- zero the tail [total*W, L*W) ----------------
        int zb  = blockIdx.x - point_blocks;
        int tid = zb * 256 + threadIdx.x;
        int stride = zero_blocks * 256;
        int total = g_off[N];
        size_t start = (size_t)total * W;
        size_t end   = (size_t)L * W;
        if (start >= end) { /* nothing */ }
        else {
            size_t start4 = (start + 3) & ~(size_t)3;   // out_group is 16B aligned
            if (start4 > end) start4 = end;
            // scalar head (<=3 elements)
            if (tid < (int)(start4 - start)) out_group[start + tid] = 0.f;
            // vector body
            float4 z4 = make_float4(0.f, 0.f, 0.f, 0.f);
            float4* o4 = (float4*)out_group;
            size_t i0 = start4 >> 2, i1 = end >> 2;
            for (size_t i = i0 + tid; i < i1; i += stride) o4[i] = z4;
            // scalar tail (<=3 elements)
            size_t rem = end & 3;
            if (tid < (int)rem) out_group[(i1 << 2) + tid] = 0.f;
        }
        if (has_idx) {
            for (int i = total + tid; i < L; i += stride) out_idx[i] = 0.f;
        }
    }
}

// ---------------------------------------------------------------------------
// Generic fallback gather (any W/C): warp per slot, row-wise (rarely used).
// ---------------------------------------------------------------------------
__global__ void __launch_bounds__(256) gather_generic_kernel(
        const float* __restrict__ xyz,
        const float* __restrict__ new_xyz,
        const float* __restrict__ feat,
        float* __restrict__ out_group,
        float* __restrict__ out_idx,
        int N, int C, int has_idx) {
    int gw   = (blockIdx.x * blockDim.x + threadIdx.x) >> 5;
    int lane = threadIdx.x & 31;
    int L = N * NSAMPLE;
    if (gw >= L) return;
    int total = g_off[N];
    int W = 3 + C;

    int n = gw >> 5;
    int s = gw & (NSAMPLE - 1);
    if (s < g_cnt[n]) {
        int pos = g_off[n] + s;
        int gi  = g_ball[n * NSAMPLE + s];
        float* row = out_group + (size_t)pos * W;
        for (int c = lane; c < W; c += 32) {
            float v;
            if (c < 3) v = __fsub_rn(xyz[3 * n + c], new_xyz[3 * (size_t)gi + c]);
            else       v = feat[(size_t)n * C + (c - 3)];
            row[c] = v;
        }
        if (lane == 0 && has_idx) out_idx[pos] = (float)gi;
    }
    if (gw >= total) {
        float* row = out_group + (size_t)gw * W;
        for (int c = lane; c < W; c += 32) row[c] = 0.f;
        if (lane == 0 && has_idx) out_idx[gw] = 0.f;
    }
}

// ---------------------------------------------------------------------------
extern "C" void kernel_launch(void* const* d_in, const int* in_sizes, int n_in,
                              void* d_out, int out_size) {
    const float* xyz      = (const float*)d_in[0];
    const float* new_xyz  = (const float*)d_in[2];
    const float* rois     = (const float*)d_in[3];
    const float* features = (const float*)d_in[4];

    int N  = in_sizes[0] / 3;
    int B  = in_sizes[1];
    int M  = in_sizes[3] / (7 * B);
    int K  = in_sizes[2] / (3 * B * M);
    int C  = in_sizes[4] / N;
    int Nb = N / B;
    int L  = N * NSAMPLE;
    int W  = 3 + C;

    float* out = (float*)d_out;
    int has_idx = (out_size >= L * W + L) ? 1 : 0;
    float* out_idx = out + (size_t)L * W;

    // 1. fused mask + ordered ball query + count + (last block) scan
    {
        int blocks = (N + 7) / 8;          // 8 warps per 256-thread block
        query_scan_kernel<<<blocks, 256>>>(xyz, new_xyz, rois, N, Nb, M, K);
    }
    // 2. fused gather + concurrent tail-zero
    if (C == 32) {
        int point_blocks = (N + 7) / 8;    // warp per point, 8 warps/block
        int zero_blocks  = 512;
        gather35_kernel<<<point_blocks + zero_blocks, 256>>>(
            xyz, new_xyz, features, out, out_idx,
            N, has_idx, point_blocks, zero_blocks, L);
    } else {
        int blocks = (L * 32 + 255) / 256;
        gather_generic_kernel<<<blocks, 256>>>(xyz, new_xyz, features, out, out_idx,
                                               N, C, has_idx);
    }
}